// round 3
// baseline (speedup 1.0000x reference)
#include <cuda_runtime.h>
#include <cuda_bf16.h>
#include <cfloat>
#include <cub/block/block_radix_sort.cuh>

// Problem constants
constexpr int L   = 8192;   // row length
constexpr int NB  = 65;     // bins / quantile edges
constexpr int NT  = 512;    // threads per block
constexpr int IPT = 16;     // items per thread (NT*IPT == L)

using Sorter = cub::BlockRadixSort<float, NT, IPT>;

// Dynamic shared memory: union of { Sorter::TempStorage , float sorted[L] }
constexpr size_t A_RAW   = (sizeof(typename Sorter::TempStorage) > (size_t)L * sizeof(float))
                               ? sizeof(typename Sorter::TempStorage)
                               : (size_t)L * sizeof(float);
constexpr size_t SMEM_TOTAL = (A_RAW + 127) & ~(size_t)127;

__global__ __launch_bounds__(NT) void mtf_kernel(const float* __restrict__ x,
                                                 float* __restrict__ out)
{
    extern __shared__ char smem_raw[];
    float* sorted = reinterpret_cast<float*>(smem_raw);

    __shared__ float s_edges[128];          // 65 edges + INF padding (branchless search)
    __shared__ int   s_first, s_last;
    __shared__ unsigned char s_firstbin[NT];

    const int row = blockIdx.x;
    const float* __restrict__ xr = x + (size_t)row * L;
    const int t = threadIdx.x;

    if (t == 0) { s_first = L; s_last = -1; }
    // INF-pad the upper half of the edge table once
    if (t >= NB && t < 128) s_edges[t] = FLT_MAX;
    __syncthreads();

    // ---- Phase A: load row (blocked), find first/last nonzero ----
    float keys[IPT];
    int lmin = L, lmax = -1;
#pragma unroll
    for (int i = 0; i < IPT; ++i) {
        int idx = t * IPT + i;
        float v = xr[idx];
        keys[i] = v;
        if (v != 0.0f) {
            if (idx < lmin) lmin = idx;
            if (idx > lmax) lmax = idx;
        }
    }
    if (lmin < L)  atomicMin(&s_first, lmin);
    if (lmax >= 0) atomicMax(&s_last,  lmax);
    __syncthreads();

    const int first = s_first;
    const int last  = s_last;
    const bool any  = (last >= 0);
    const int m     = any ? (last - first + 1) : 0;

    // ---- Phase B: mask out-of-range -> FLT_MAX, block radix sort ----
#pragma unroll
    for (int i = 0; i < IPT; ++i) {
        int idx = t * IPT + i;
        if (!(any && idx >= first && idx <= last)) keys[i] = FLT_MAX;
    }
    __syncthreads();
    Sorter(*reinterpret_cast<typename Sorter::TempStorage*>(smem_raw)).Sort(keys);
    __syncthreads();
#pragma unroll
    for (int i = 0; i < IPT; ++i) sorted[t * IPT + i] = keys[i];
    __syncthreads();

    // ---- Phase C: 65 quantile edges (fp32 math mirrors jnp exactly) ----
    if (t < NB) {
        float q;
        if (m > 0) {
            const float step = 1.0f / 65.0f;           // linspace step in fp32
            float qlev = (float)t * step;
            float pos  = qlev * (float)(m - 1);
            int   lo   = (int)floorf(pos);
            int   hi   = (int)ceilf(pos);
            float frac = pos - (float)lo;
            float vlo  = sorted[lo];
            float vhi  = sorted[hi];
            q = vlo + frac * (vhi - vlo);
        } else {
            q = 0.0f;
        }
        s_edges[t] = q;
    }
    __syncthreads();

    // ---- Phase D: bin every value, branchless 7-step search over padded table ----
    int binreg[IPT];
#pragma unroll
    for (int i = 0; i < IPT; ++i) {
        int idx = t * IPT + i;
        float v = xr[idx];
        // count of (edges <= v) over monotone 128-entry table (top half = +INF)
        int pos = 0;
#pragma unroll
        for (int s = 64; s >= 1; s >>= 1)
            if (s_edges[pos + s - 1] <= v) pos += s;
        int b = pos;
        if (b > NB - 1) b = NB - 1;
        binreg[i] = b;
    }
    s_firstbin[t] = (unsigned char)binreg[0];
    __syncthreads();

    // ---- Phase E: transitions straight to GMEM via fire-and-forget REDG ----
    // d_out zeroed by cudaMemsetAsync before this kernel. Every add to a cell
    // adds the same constant, so the result is order-independent (deterministic).
    const float inv = 1.0f / (float)(L - 1);
    float* __restrict__ outr = out + (size_t)row * NB * NB;
#pragma unroll
    for (int i = 0; i < IPT - 1; ++i)
        atomicAdd(&outr[binreg[i] * NB + binreg[i + 1]], inv);
    // boundary pair to the next thread's first element
    if (t < NT - 1)
        atomicAdd(&outr[binreg[IPT - 1] * NB + (int)s_firstbin[t + 1]], inv);
}

extern "C" void kernel_launch(void* const* d_in, const int* in_sizes, int n_in,
                              void* d_out, int out_size)
{
    const float* x = (const float*)d_in[0];
    float* out = (float*)d_out;
    const int rows = in_sizes[0] / L;   // 512*4 = 2048

    cudaMemsetAsync(d_out, 0, (size_t)out_size * sizeof(float));

    cudaFuncSetAttribute(mtf_kernel,
                         cudaFuncAttributeMaxDynamicSharedMemorySize,
                         (int)SMEM_TOTAL);
    mtf_kernel<<<rows, NT, SMEM_TOTAL>>>(x, out);
}

// round 4
// speedup vs baseline: 1.1636x; 1.1636x over previous
#include <cuda_runtime.h>
#include <cuda_bf16.h>
#include <cfloat>
#include <cub/block/block_radix_sort.cuh>

// Problem constants
constexpr int L    = 8192;   // row length
constexpr int HALF = 4096;   // per-sub-sort size
constexpr int NB   = 65;     // bins / quantile edges
constexpr int NT   = 512;    // threads per block
constexpr int IPT  = 8;      // items per thread per sub-sort (NT*IPT == HALF)
constexpr int IPB  = 16;     // items per thread for binning (NT*IPB == L)

using Sorter = cub::BlockRadixSort<float, NT, IPT>;

// Shared layout:
//   [ sA : 4096 floats ]
//   [ region2 : union { Sorter::TempStorage , sB : 4096 floats } ]
//   [ hist : NB*NB uint ]
constexpr size_t SB_BYTES = (size_t)HALF * sizeof(float);
constexpr size_t R2_RAW   = (sizeof(typename Sorter::TempStorage) > SB_BYTES)
                                ? sizeof(typename Sorter::TempStorage) : SB_BYTES;
constexpr size_t R2_BYTES = (R2_RAW + 127) & ~(size_t)127;
constexpr size_t SMEM_TOTAL = SB_BYTES + R2_BYTES + (size_t)NB * NB * sizeof(unsigned);

// k-th smallest (0-indexed) of the union of two sorted ascending arrays A[n], B[n].
__device__ __forceinline__ float select2(const float* __restrict__ A,
                                         const float* __restrict__ B,
                                         int n, int k)
{
    int ilo = (k + 1 - n > 0) ? (k + 1 - n) : 0;
    int ihi = (k + 1 < n) ? (k + 1) : n;
    for (;;) {
        int i = (ilo + ihi) >> 1;   // take i from A, j from B
        int j = k + 1 - i;
        float Aim1 = (i > 0) ? A[i - 1] : -FLT_MAX;
        float Ai   = (i < n) ? A[i]     :  FLT_MAX;
        float Bjm1 = (j > 0) ? B[j - 1] : -FLT_MAX;
        float Bj   = (j < n) ? B[j]     :  FLT_MAX;
        if (Aim1 > Bj)       ihi = i - 1;
        else if (Bjm1 > Ai)  ilo = i + 1;
        else return fmaxf(Aim1, Bjm1);
    }
}

__global__ __launch_bounds__(NT, 2) void mtf_kernel(const float* __restrict__ x,
                                                    float* __restrict__ out)
{
    extern __shared__ char smem_raw[];
    float* sA = reinterpret_cast<float*>(smem_raw);
    char*  region2 = smem_raw + SB_BYTES;
    float* sB = reinterpret_cast<float*>(region2);
    typename Sorter::TempStorage* temp =
        reinterpret_cast<typename Sorter::TempStorage*>(region2);
    unsigned* hist = reinterpret_cast<unsigned*>(region2 + R2_BYTES);

    __shared__ float s_edges[128];   // 65 edges + INF padding (branchless search)
    __shared__ int   s_first, s_last;
    __shared__ unsigned char s_firstbin[NT];

    const int row = blockIdx.x;
    const float* __restrict__ xr = x + (size_t)row * L;
    const int t = threadIdx.x;

    if (t == 0) { s_first = L; s_last = -1; }
    if (t >= NB && t < 128) s_edges[t] = FLT_MAX;
    for (int i = t; i < NB * NB; i += NT) hist[i] = 0u;
    __syncthreads();

    // ---- Phase A: scan both halves for first/last nonzero; keep half-A keys ----
    float keys[IPT];
    int lmin = L, lmax = -1;
#pragma unroll
    for (int i = 0; i < IPT; ++i) {
        int idx = t * IPT + i;
        float v = xr[idx];
        keys[i] = v;
        if (v != 0.0f) { if (idx < lmin) lmin = idx; if (idx > lmax) lmax = idx; }
    }
#pragma unroll
    for (int i = 0; i < IPT; ++i) {
        int idx = HALF + t * IPT + i;
        float v = xr[idx];
        if (v != 0.0f) { if (idx < lmin) lmin = idx; if (idx > lmax) lmax = idx; }
    }
    if (lmin < L)  atomicMin(&s_first, lmin);
    if (lmax >= 0) atomicMax(&s_last,  lmax);
    __syncthreads();

    const int first = s_first;
    const int last  = s_last;
    const bool any  = (last >= 0);
    const int m     = any ? (last - first + 1) : 0;

    // ---- Phase B1: sort half A (temp aliases sB region — sB unwritten yet) ----
#pragma unroll
    for (int i = 0; i < IPT; ++i) {
        int idx = t * IPT + i;
        if (!(any && idx >= first && idx <= last)) keys[i] = FLT_MAX;
    }
    __syncthreads();
    Sorter(*temp).Sort(keys);
    __syncthreads();
#pragma unroll
    for (int i = 0; i < IPT; ++i) sA[t * IPT + i] = keys[i];   // sA disjoint from temp

    // ---- Phase B2: sort half B ----
#pragma unroll
    for (int i = 0; i < IPT; ++i) {
        int idx = HALF + t * IPT + i;
        float v = xr[idx];
        if (!(any && idx >= first && idx <= last)) v = FLT_MAX;
        keys[i] = v;
    }
    __syncthreads();
    Sorter(*temp).Sort(keys);
    __syncthreads();                       // everyone done with temp before overwrite
#pragma unroll
    for (int i = 0; i < IPT; ++i) sB[t * IPT + i] = keys[i];   // sB overwrites temp: OK
    __syncthreads();

    // ---- Phase C: 65 quantile edges via dual-array selection (fp32 mirrors jnp) ----
    if (t < NB) {
        float q;
        if (m > 0) {
            const float step = 1.0f / 65.0f;
            float qlev = (float)t * step;
            float pos  = qlev * (float)(m - 1);
            int   lo   = (int)floorf(pos);
            int   hi   = (int)ceilf(pos);
            float frac = pos - (float)lo;
            float vlo  = select2(sA, sB, HALF, lo);
            float vhi  = (hi == lo) ? vlo : select2(sA, sB, HALF, hi);
            q = vlo + frac * (vhi - vlo);
        } else {
            q = 0.0f;
        }
        s_edges[t] = q;
    }
    __syncthreads();

    // ---- Phase D: bin every value, branchless 7-step search over padded table ----
    int binreg[IPB];
#pragma unroll
    for (int i = 0; i < IPB; ++i) {
        int idx = t * IPB + i;
        float v = xr[idx];
        int pos = 0;
#pragma unroll
        for (int s = 64; s >= 1; s >>= 1)
            if (s_edges[pos + s - 1] <= v) pos += s;
        binreg[i] = (pos > NB - 1) ? (NB - 1) : pos;
    }
    s_firstbin[t] = (unsigned char)binreg[0];
    __syncthreads();

    // ---- Phase E: transition histogram in shared memory ----
#pragma unroll
    for (int i = 0; i < IPB - 1; ++i)
        atomicAdd(&hist[binreg[i] * NB + binreg[i + 1]], 1u);
    if (t < NT - 1)
        atomicAdd(&hist[binreg[IPB - 1] * NB + (int)s_firstbin[t + 1]], 1u);
    __syncthreads();

    // ---- Phase F: normalize + store ----
    const float inv = 1.0f / (float)(L - 1);
    float* outr = out + (size_t)row * NB * NB;
    for (int i = t; i < NB * NB; i += NT)
        outr[i] = (float)hist[i] * inv;
}

extern "C" void kernel_launch(void* const* d_in, const int* in_sizes, int n_in,
                              void* d_out, int out_size)
{
    const float* x = (const float*)d_in[0];
    float* out = (float*)d_out;
    const int rows = in_sizes[0] / L;   // 512*4 = 2048

    cudaFuncSetAttribute(mtf_kernel,
                         cudaFuncAttributeMaxDynamicSharedMemorySize,
                         (int)SMEM_TOTAL);
    mtf_kernel<<<rows, NT, SMEM_TOTAL>>>(x, out);
}

// round 5
// speedup vs baseline: 1.2739x; 1.0948x over previous
#include <cuda_runtime.h>
#include <cuda_bf16.h>
#include <cfloat>

// Problem constants
constexpr int L   = 8192;   // row length
constexpr int NB  = 65;     // bins / quantile edges
constexpr int NT  = 512;    // threads per block
constexpr int IPT = 16;     // items per thread (NT*IPT == L)
constexpr int RUN = 512;    // per-warp sorted run (32 lanes * 16 items)

// Shared layout: bufA[8192] | bufB[8192] | hist[NB*NB]
constexpr size_t BUF_BYTES  = (size_t)L * sizeof(float);
constexpr size_t SMEM_TOTAL = 2 * BUF_BYTES + (size_t)NB * NB * sizeof(unsigned);

// ---------------- bitonic helpers (warp sorts 512 elems, 16/thread) ----------
template <int J>
__device__ __forceinline__ void inthread_stage(float (&v)[IPT], int k, int lane)
{
#pragma unroll
    for (int i = 0; i < IPT; ++i) {
        if ((i & J) != 0) continue;          // compile-time
        const int q = i | J;
        const int p = (lane << 4) | i;       // index within 512-run
        const bool asc = ((p & k) == 0);
        float a = v[i], b = v[q];
        float mn = fminf(a, b), mx = fmaxf(a, b);
        v[i] = asc ? mn : mx;
        v[q] = asc ? mx : mn;
    }
}

__device__ __forceinline__ void cross_stage(float (&v)[IPT], int k, int j, int lane)
{
    const int  lmask = j >> 4;               // lane xor distance
    const bool up    = (lane & lmask) == 0;  // we are the lower partner
#pragma unroll
    for (int i = 0; i < IPT; ++i) {
        const int p = (lane << 4) | i;
        const bool asc = ((p & k) == 0);     // uniform per thread for k>=16
        float other = __shfl_xor_sync(0xffffffffu, v[i], lmask);
        const bool keepMin = (asc == up);
        v[i] = keepMin ? fminf(v[i], other) : fmaxf(v[i], other);
    }
}

__device__ __forceinline__ void warp_bitonic_512(float (&v)[IPT], int lane)
{
    for (int k = 2; k <= RUN; k <<= 1) {
        for (int j = k >> 1; j >= 16; j >>= 1)
            cross_stage(v, k, j, lane);
        if (k >= 16) {
            inthread_stage<8>(v, k, lane);
            inthread_stage<4>(v, k, lane);
            inthread_stage<2>(v, k, lane);
            inthread_stage<1>(v, k, lane);
        } else if (k == 8) {
            inthread_stage<4>(v, k, lane);
            inthread_stage<2>(v, k, lane);
            inthread_stage<1>(v, k, lane);
        } else if (k == 4) {
            inthread_stage<2>(v, k, lane);
            inthread_stage<1>(v, k, lane);
        } else {  // k == 2
            inthread_stage<1>(v, k, lane);
        }
    }
}

// ---------------- merge-path round: runs of length R -> 2R --------------------
template <int R>
__device__ __forceinline__ void merge_round(const float* __restrict__ src,
                                            float* __restrict__ dst, int t)
{
    const int seg0    = t << 4;              // 16 outputs per thread
    const int pairlen = R << 1;
    const int pair    = seg0 / pairlen;      // compile-time shift
    const int o       = seg0 & (pairlen - 1);
    const float* __restrict__ A = src + pair * pairlen;
    const float* __restrict__ B = A + R;

    // merge-path partition (A takes ties)
    int alo = o - R; if (alo < 0) alo = 0;
    int ahi = (o < R) ? o : R;
    while (alo < ahi) {
        int amid = (alo + ahi) >> 1;
        if (A[amid] <= B[o - 1 - amid]) alo = amid + 1; else ahi = amid;
    }
    int a = alo, b = o - alo;

    float av = (a < R) ? A[a] : FLT_MAX;
    float bv = (b < R) ? B[b] : FLT_MAX;
    float* __restrict__ outp = dst + pair * pairlen + o;
#pragma unroll
    for (int i = 0; i < IPT; ++i) {
        bool takeA = (a < R) && (b >= R || av <= bv);
        float ov = takeA ? av : bv;
        if (takeA) { ++a; av = (a < R) ? A[a] : FLT_MAX; }
        else       { ++b; bv = (b < R) ? B[b] : FLT_MAX; }
        outp[i] = ov;
    }
}

// k-th smallest (0-indexed) of the union of two sorted ascending arrays A[n], B[n].
__device__ __forceinline__ float select2(const float* __restrict__ A,
                                         const float* __restrict__ B,
                                         int n, int k)
{
    int ilo = (k + 1 - n > 0) ? (k + 1 - n) : 0;
    int ihi = (k + 1 < n) ? (k + 1) : n;
    for (;;) {
        int i = (ilo + ihi) >> 1;   // take i from A, j from B
        int j = k + 1 - i;
        float Aim1 = (i > 0) ? A[i - 1] : -FLT_MAX;
        float Ai   = (i < n) ? A[i]     :  FLT_MAX;
        float Bjm1 = (j > 0) ? B[j - 1] : -FLT_MAX;
        float Bj   = (j < n) ? B[j]     :  FLT_MAX;
        if (Aim1 > Bj)       ihi = i - 1;
        else if (Bjm1 > Ai)  ilo = i + 1;
        else return fmaxf(Aim1, Bjm1);
    }
}

__global__ __launch_bounds__(NT, 2) void mtf_kernel(const float* __restrict__ x,
                                                    float* __restrict__ out)
{
    extern __shared__ char smem_raw[];
    float*    bufA = reinterpret_cast<float*>(smem_raw);
    float*    bufB = reinterpret_cast<float*>(smem_raw + BUF_BYTES);
    unsigned* hist = reinterpret_cast<unsigned*>(smem_raw + 2 * BUF_BYTES);

    __shared__ float s_edges[128];   // 65 edges + INF padding (branchless search)
    __shared__ int   s_first, s_last;
    __shared__ unsigned char s_firstbin[NT];

    const int row = blockIdx.x;
    const float* __restrict__ xr = x + (size_t)row * L;
    const int t    = threadIdx.x;
    const int lane = t & 31;

    if (t == 0) { s_first = L; s_last = -1; }
    if (t >= NB && t < 128) s_edges[t] = FLT_MAX;
    for (int i = t; i < NB * NB; i += NT) hist[i] = 0u;
    __syncthreads();

    // ---- Phase A: load row (blocked 16/thread), find first/last nonzero ----
    float v[IPT];
    int lmin = L, lmax = -1;
#pragma unroll
    for (int i = 0; i < IPT; ++i) {
        int idx = t * IPT + i;
        float val = xr[idx];
        v[i] = val;
        if (val != 0.0f) { if (idx < lmin) lmin = idx; if (idx > lmax) lmax = idx; }
    }
    if (lmin < L)  atomicMin(&s_first, lmin);
    if (lmax >= 0) atomicMax(&s_last,  lmax);
    __syncthreads();

    const int first = s_first;
    const int last  = s_last;
    const bool any  = (last >= 0);
    const int m     = any ? (last - first + 1) : 0;

    // ---- Phase B: mask -> FLT_MAX, per-warp bitonic sort (registers only) ----
#pragma unroll
    for (int i = 0; i < IPT; ++i) {
        int idx = t * IPT + i;
        if (!(any && idx >= first && idx <= last)) v[i] = FLT_MAX;
    }
    warp_bitonic_512(v, lane);
    // store 16 sorted runs of 512: global pos = warp*512 + lane*16 + i = t*16+i
#pragma unroll
    for (int i = 0; i < IPT; ++i) bufA[t * IPT + i] = v[i];
    __syncthreads();

    // ---- Phase B2: three merge rounds: 512 -> 1024 -> 2048 -> 4096 ----
    merge_round<512>(bufA, bufB, t);  __syncthreads();
    merge_round<1024>(bufB, bufA, t); __syncthreads();
    merge_round<2048>(bufA, bufB, t); __syncthreads();
    // two sorted runs of 4096 now in bufB[0..4096) and bufB[4096..8192)

    const float* sA2 = bufB;
    const float* sB2 = bufB + 4096;

    // ---- Phase C: 65 quantile edges via dual-array selection (fp32 = jnp) ----
    if (t < NB) {
        float q;
        if (m > 0) {
            const float step = 1.0f / 65.0f;
            float qlev = (float)t * step;
            float pos  = qlev * (float)(m - 1);
            int   lo   = (int)floorf(pos);
            int   hi   = (int)ceilf(pos);
            float frac = pos - (float)lo;
            float vlo  = select2(sA2, sB2, 4096, lo);
            float vhi  = (hi == lo) ? vlo : select2(sA2, sB2, 4096, hi);
            q = vlo + frac * (vhi - vlo);
        } else {
            q = 0.0f;
        }
        s_edges[t] = q;
    }
    __syncthreads();

    // ---- Phase D: bin every value, branchless 7-step search over padded table ----
    int binreg[IPT];
#pragma unroll
    for (int i = 0; i < IPT; ++i) {
        int idx = t * IPT + i;
        float val = xr[idx];
        int pos = 0;
#pragma unroll
        for (int s = 64; s >= 1; s >>= 1)
            if (s_edges[pos + s - 1] <= val) pos += s;
        binreg[i] = (pos > NB - 1) ? (NB - 1) : pos;
    }
    s_firstbin[t] = (unsigned char)binreg[0];
    __syncthreads();

    // ---- Phase E: transition histogram in shared memory ----
#pragma unroll
    for (int i = 0; i < IPT - 1; ++i)
        atomicAdd(&hist[binreg[i] * NB + binreg[i + 1]], 1u);
    if (t < NT - 1)
        atomicAdd(&hist[binreg[IPT - 1] * NB + (int)s_firstbin[t + 1]], 1u);
    __syncthreads();

    // ---- Phase F: normalize + store ----
    const float inv = 1.0f / (float)(L - 1);
    float* outr = out + (size_t)row * NB * NB;
    for (int i = t; i < NB * NB; i += NT)
        outr[i] = (float)hist[i] * inv;
}

extern "C" void kernel_launch(void* const* d_in, const int* in_sizes, int n_in,
                              void* d_out, int out_size)
{
    const float* x = (const float*)d_in[0];
    float* out = (float*)d_out;
    const int rows = in_sizes[0] / L;   // 512*4 = 2048

    cudaFuncSetAttribute(mtf_kernel,
                         cudaFuncAttributeMaxDynamicSharedMemorySize,
                         (int)SMEM_TOTAL);
    mtf_kernel<<<rows, NT, SMEM_TOTAL>>>(x, out);
}

// round 6
// speedup vs baseline: 1.3372x; 1.0497x over previous
#include <cuda_runtime.h>
#include <cuda_bf16.h>
#include <cfloat>

// Problem constants
constexpr int L   = 8192;   // row length
constexpr int NB  = 65;     // bins / quantile edges
constexpr int NT  = 512;    // threads per block
constexpr int IPT = 16;     // items per thread (NT*IPT == L)
constexpr int RUN = 512;    // per-warp sorted run (32 lanes * 16 items)

// Shared layout: bufA[8192] | bufB[8192] | hist[NB*NB]
constexpr size_t BUF_BYTES  = (size_t)L * sizeof(float);
constexpr size_t SMEM_TOTAL = 2 * BUF_BYTES + (size_t)NB * NB * sizeof(unsigned);

// ---------------- bitonic helpers (warp sorts 512 elems, 16/thread) ----------
template <int J>
__device__ __forceinline__ void inthread_stage(float (&v)[IPT], int k, int lane)
{
#pragma unroll
    for (int i = 0; i < IPT; ++i) {
        if ((i & J) != 0) continue;          // compile-time
        const int q = i | J;
        const int p = (lane << 4) | i;       // index within 512-run
        const bool asc = ((p & k) == 0);
        float a = v[i], b = v[q];
        float mn = fminf(a, b), mx = fmaxf(a, b);
        v[i] = asc ? mn : mx;
        v[q] = asc ? mx : mn;
    }
}

__device__ __forceinline__ void cross_stage(float (&v)[IPT], int k, int j, int lane)
{
    const int  lmask = j >> 4;               // lane xor distance
    const bool up    = (lane & lmask) == 0;  // we are the lower partner
#pragma unroll
    for (int i = 0; i < IPT; ++i) {
        const int p = (lane << 4) | i;
        const bool asc = ((p & k) == 0);     // uniform per thread for k>=16
        float other = __shfl_xor_sync(0xffffffffu, v[i], lmask);
        const bool keepMin = (asc == up);
        v[i] = keepMin ? fminf(v[i], other) : fmaxf(v[i], other);
    }
}

__device__ __forceinline__ void warp_bitonic_512(float (&v)[IPT], int lane)
{
    for (int k = 2; k <= RUN; k <<= 1) {
        for (int j = k >> 1; j >= 16; j >>= 1)
            cross_stage(v, k, j, lane);
        if (k >= 16) {
            inthread_stage<8>(v, k, lane);
            inthread_stage<4>(v, k, lane);
            inthread_stage<2>(v, k, lane);
            inthread_stage<1>(v, k, lane);
        } else if (k == 8) {
            inthread_stage<4>(v, k, lane);
            inthread_stage<2>(v, k, lane);
            inthread_stage<1>(v, k, lane);
        } else if (k == 4) {
            inthread_stage<2>(v, k, lane);
            inthread_stage<1>(v, k, lane);
        } else {  // k == 2
            inthread_stage<1>(v, k, lane);
        }
    }
}

// ---------------- merge-path round: runs of length R -> 2R --------------------
template <int R>
__device__ __forceinline__ void merge_round(const float* __restrict__ src,
                                            float* __restrict__ dst, int t)
{
    const int seg0    = t << 4;              // 16 outputs per thread
    const int pairlen = R << 1;
    const int pair    = seg0 / pairlen;      // compile-time shift
    const int o       = seg0 & (pairlen - 1);
    const float* __restrict__ A = src + pair * pairlen;
    const float* __restrict__ B = A + R;

    // merge-path partition (A takes ties)
    int alo = o - R; if (alo < 0) alo = 0;
    int ahi = (o < R) ? o : R;
    while (alo < ahi) {
        int amid = (alo + ahi) >> 1;
        if (A[amid] <= B[o - 1 - amid]) alo = amid + 1; else ahi = amid;
    }
    int a = alo, b = o - alo;

    float av = (a < R) ? A[a] : FLT_MAX;
    float bv = (b < R) ? B[b] : FLT_MAX;
    float* __restrict__ outp = dst + pair * pairlen + o;
#pragma unroll
    for (int i = 0; i < IPT; ++i) {
        bool takeA = (a < R) && (b >= R || av <= bv);
        float ov = takeA ? av : bv;
        if (takeA) { ++a; av = (a < R) ? A[a] : FLT_MAX; }
        else       { ++b; bv = (b < R) ? B[b] : FLT_MAX; }
        outp[i] = ov;
    }
}

// k-th smallest (0-indexed) of the union of two sorted ascending arrays A[n], B[n].
__device__ __forceinline__ float select2(const float* __restrict__ A,
                                         const float* __restrict__ B,
                                         int n, int k)
{
    int ilo = (k + 1 - n > 0) ? (k + 1 - n) : 0;
    int ihi = (k + 1 < n) ? (k + 1) : n;
    for (;;) {
        int i = (ilo + ihi) >> 1;   // take i from A, j from B
        int j = k + 1 - i;
        float Aim1 = (i > 0) ? A[i - 1] : -FLT_MAX;
        float Ai   = (i < n) ? A[i]     :  FLT_MAX;
        float Bjm1 = (j > 0) ? B[j - 1] : -FLT_MAX;
        float Bj   = (j < n) ? B[j]     :  FLT_MAX;
        if (Aim1 > Bj)       ihi = i - 1;
        else if (Bjm1 > Ai)  ilo = i + 1;
        else return fmaxf(Aim1, Bjm1);
    }
}

__global__ __launch_bounds__(NT, 2) void mtf_kernel(const float* __restrict__ x,
                                                    float* __restrict__ out)
{
    extern __shared__ char smem_raw[];
    float*    bufA = reinterpret_cast<float*>(smem_raw);
    float*    bufB = reinterpret_cast<float*>(smem_raw + BUF_BYTES);
    unsigned* hist = reinterpret_cast<unsigned*>(smem_raw + 2 * BUF_BYTES);

    __shared__ float s_edges[NB];
    __shared__ float s_eytz[128];    // BFS (Eytzinger) layout of 127 padded edges
    __shared__ int   s_first, s_last;
    __shared__ unsigned char s_firstbin[NT];

    const int row = blockIdx.x;
    const float* __restrict__ xr = x + (size_t)row * L;
    const float4* __restrict__ xr4 = reinterpret_cast<const float4*>(xr);
    const int t    = threadIdx.x;
    const int lane = t & 31;

    if (t == 0) { s_first = L; s_last = -1; }
    for (int i = t; i < NB * NB; i += NT) hist[i] = 0u;
    __syncthreads();

    // ---- Phase A: vectorized load (4x LDG.128), find first/last nonzero ----
    float v[IPT];
    int lmin = L, lmax = -1;
#pragma unroll
    for (int j = 0; j < 4; ++j) {
        float4 p = xr4[t * 4 + j];
        int base = t * IPT + j * 4;
        v[j * 4 + 0] = p.x; v[j * 4 + 1] = p.y;
        v[j * 4 + 2] = p.z; v[j * 4 + 3] = p.w;
#pragma unroll
        for (int c = 0; c < 4; ++c) {
            float val = v[j * 4 + c];
            int idx = base + c;
            if (val != 0.0f) { if (idx < lmin) lmin = idx; if (idx > lmax) lmax = idx; }
        }
    }
    if (lmin < L)  atomicMin(&s_first, lmin);
    if (lmax >= 0) atomicMax(&s_last,  lmax);
    __syncthreads();

    const int first = s_first;
    const int last  = s_last;
    const bool any  = (last >= 0);
    const int m     = any ? (last - first + 1) : 0;

    // ---- Phase B: mask -> FLT_MAX, per-warp bitonic sort (registers only) ----
#pragma unroll
    for (int i = 0; i < IPT; ++i) {
        int idx = t * IPT + i;
        if (!(any && idx >= first && idx <= last)) v[i] = FLT_MAX;
    }
    warp_bitonic_512(v, lane);
#pragma unroll
    for (int i = 0; i < IPT; ++i) bufA[t * IPT + i] = v[i];
    __syncthreads();

    // ---- Phase B2: three merge rounds: 512 -> 1024 -> 2048 -> 4096 ----
    merge_round<512>(bufA, bufB, t);  __syncthreads();
    merge_round<1024>(bufB, bufA, t); __syncthreads();
    merge_round<2048>(bufA, bufB, t); __syncthreads();
    // two sorted runs of 4096 now in bufB[0..4096) and bufB[4096..8192)

    const float* sA2 = bufB;
    const float* sB2 = bufB + 4096;

    // ---- Phase C: 65 quantile edges via dual-array selection (fp32 = jnp) ----
    if (t < NB) {
        float q;
        if (m > 0) {
            const float step = 1.0f / 65.0f;
            float qlev = (float)t * step;
            float pos  = qlev * (float)(m - 1);
            int   lo   = (int)floorf(pos);
            int   hi   = (int)ceilf(pos);
            float frac = pos - (float)lo;
            float vlo  = select2(sA2, sB2, 4096, lo);
            float vhi  = (hi == lo) ? vlo : select2(sA2, sB2, 4096, hi);
            q = vlo + frac * (vhi - vlo);
        } else {
            q = 0.0f;
        }
        s_edges[t] = q;
    }
    __syncthreads();

    // ---- Phase C2: build Eytzinger tree over 127 padded edges ----
    // node i (1..127) at depth d; its in-order 0-based index:
    //   idx0 = (((i - 2^d)*2 + 1) << (6-d)) - 1
    if (t >= 1 && t < 128) {
        int d    = 31 - __clz((unsigned)t);
        int idx0 = ((((t - (1 << d)) << 1) + 1) << (6 - d)) - 1;
        s_eytz[t] = (idx0 < NB) ? s_edges[idx0] : FLT_MAX;
    }
    __syncthreads();

    // ---- Phase D: reload (vectorized), bin via conflict-free Eytzinger search ----
    int binreg[IPT];
#pragma unroll
    for (int j = 0; j < 4; ++j) {
        float4 p = xr4[t * 4 + j];
        float vals[4] = {p.x, p.y, p.z, p.w};
#pragma unroll
        for (int c = 0; c < 4; ++c) {
            float val = vals[c];
            unsigned node = 1;
#pragma unroll
            for (int s = 0; s < 7; ++s)
                node = 2u * node + (s_eytz[node] <= val ? 1u : 0u);
            int b = (int)node - 128;        // count of edges <= val
            binreg[j * 4 + c] = (b > NB - 1) ? (NB - 1) : b;
        }
    }
    s_firstbin[t] = (unsigned char)binreg[0];
    __syncthreads();

    // ---- Phase E: transition histogram in shared memory ----
#pragma unroll
    for (int i = 0; i < IPT - 1; ++i)
        atomicAdd(&hist[binreg[i] * NB + binreg[i + 1]], 1u);
    if (t < NT - 1)
        atomicAdd(&hist[binreg[IPT - 1] * NB + (int)s_firstbin[t + 1]], 1u);
    __syncthreads();

    // ---- Phase F: normalize + store ----
    const float inv = 1.0f / (float)(L - 1);
    float* outr = out + (size_t)row * NB * NB;
    for (int i = t; i < NB * NB; i += NT)
        outr[i] = (float)hist[i] * inv;
}

extern "C" void kernel_launch(void* const* d_in, const int* in_sizes, int n_in,
                              void* d_out, int out_size)
{
    const float* x = (const float*)d_in[0];
    float* out = (float*)d_out;
    const int rows = in_sizes[0] / L;   // 512*4 = 2048

    cudaFuncSetAttribute(mtf_kernel,
                         cudaFuncAttributeMaxDynamicSharedMemorySize,
                         (int)SMEM_TOTAL);
    mtf_kernel<<<rows, NT, SMEM_TOTAL>>>(x, out);
}